// round 11
// baseline (speedup 1.0000x reference)
#include <cuda_runtime.h>
#include <cstdint>

// ---------------------------------------------------------------------------
// CarryII R11: chunked zero+scatter with a ONE-PASS bucket partition.
//  partition: each edge's (s,d) -> bucket (relation, dst-chunk). Chunks are
//             sized <= ~96MB so a freshly zeroed chunk stays dirty in L2.
//  per chunk: zero chunk, then scatter ONLY that bucket's edges (red.v4).
//             REDs land on L2-dirty lines: no RFO read, and the zero write
//             merges into the single final writeback (1 DRAM transfer per
//             output line instead of up to 3 in R6).
//  Unlike R7, edges are scanned once in partition + once in their own
//  bucket -- no repeated predicated full scans.
// Feat gathers use __ldcs (evict-first) to protect chunk residency.
// ---------------------------------------------------------------------------

static constexpr int FEAT_D = 32;
static constexpr int N3C = 1500000;
static constexpr int N4C = 2000000;
static constexpr long long TOT = 2LL * N3C + 5LL * N4C;   // 13,000,000
// rel 0,1 (N3 rows): 2 chunks of 750k rows (96MB). rel 2..6 (N4): 3 chunks
// of 666,667 rows (85MB).
static constexpr long long PAIR_SLOTS = 2LL * 2 * N3C + 5LL * 3 * N4C; // 36M

__device__ int2 g_pairs[PAIR_SLOTS];
__device__ int  g_cur[21];

struct EdgePtrs {
    const int* s[7];
    const int* d[7];
    int ebase[8];
};
struct SlotBases { int b[21]; };

__device__ __forceinline__ int find_rel(const EdgePtrs& ep, int ge) {
    int r = 0;
    #pragma unroll
    for (int k = 1; k < 7; k++) r += (ge >= ep.ebase[k]);
    return r;
}

__global__ void init_cur_kernel() {
    if (threadIdx.x < 21) g_cur[threadIdx.x] = 0;
}

__global__ void partition_kernel(EdgePtrs ep, SlotBases sb) {
    int ge = blockIdx.x * blockDim.x + threadIdx.x;
    if (ge >= (int)TOT) return;
    int r = find_rel(ep, ge);
    int le = ge - ep.ebase[r];
    int s = __ldcs(ep.s[r] + le);
    int d = __ldcs(ep.d[r] + le);

    int rows = (r < 2) ? N3C : N4C;
    int nch  = (r < 2) ? 2 : 3;
    int cdiv = (rows + nch - 1) / nch;
    int c = d / cdiv;
    int bid = r * 3 + c;

    // warp-aggregated bucket push (coalesced pair writes per group)
    unsigned mask = __match_any_sync(__activemask(), bid);
    int lane = threadIdx.x & 31;
    int leader = __ffs(mask) - 1;
    int pos0 = 0;
    if (lane == leader) pos0 = atomicAdd(&g_cur[bid], __popc(mask));
    pos0 = __shfl_sync(mask, pos0, leader);
    int rank = __popc(mask & ((1u << lane) - 1));
    g_pairs[(long long)sb.b[bid] + pos0 + rank] = make_int2(s, d);
}

__global__ void zero_f4_kernel(float4* __restrict__ out, long long n4) {
    long long i = blockIdx.x * (long long)blockDim.x + threadIdx.x;
    if (i < n4) out[i] = make_float4(0.f, 0.f, 0.f, 0.f);
}

__device__ __forceinline__ void red_add_v4(float* addr, float4 v) {
    asm volatile("red.global.v4.f32.add [%0], {%1, %2, %3, %4};"
                 :: "l"(addr), "f"(v.x), "f"(v.y), "f"(v.z), "f"(v.w)
                 : "memory");
}

__device__ __forceinline__ float4 ldcs_f4(const float4* p) {
    float4 v;
    asm volatile("ld.global.cs.v4.f32 {%0, %1, %2, %3}, [%4];"
                 : "=f"(v.x), "=f"(v.y), "=f"(v.z), "=f"(v.w) : "l"(p));
    return v;
}

// 8 lanes per pair, 2 pairs per thread (j, j+half); count read from g_cur.
__global__ void scatter_bucket_kernel(const float4* __restrict__ feat,
                                      float* __restrict__ out_blk,
                                      int slot_base, int bid, int half) {
    long long gid = blockIdx.x * (long long)blockDim.x + threadIdx.x;
    int q = (int)(gid >> 3);
    if (q >= half) return;
    int sub = (int)(gid & 7);

    int cnt = __ldg(&g_cur[bid]);           // broadcast, L2-hot
    int j0 = q, j1 = q + half;
    bool p0 = (j0 < cnt), p1 = (j1 < cnt);
    if (!p0) return;                        // j0<cnt implies ordering

    int2 e0 = __ldg(&g_pairs[(long long)slot_base + j0]);
    int2 e1 = p1 ? __ldg(&g_pairs[(long long)slot_base + j1])
                 : make_int2(0, 0);

    float4 v0 = ldcs_f4(feat + (long long)e0.x * 8 + sub);
    float4 v1;
    if (p1) v1 = ldcs_f4(feat + (long long)e1.x * 8 + sub);

    red_add_v4(out_blk + (long long)e0.y * FEAT_D + sub * 4, v0);
    if (p1) red_add_v4(out_blk + (long long)e1.y * FEAT_D + sub * 4, v1);
}

extern "C" void kernel_launch(void* const* d_in, const int* in_sizes, int n_in,
                              void* d_out, int out_size) {
    const float* u2 = (const float*)d_in[0];
    const float* u3 = (const float*)d_in[1];

    EdgePtrs ep;
    ep.s[0] = (const int*)d_in[2];  ep.d[0] = (const int*)d_in[3];
    ep.s[1] = (const int*)d_in[4];  ep.d[1] = (const int*)d_in[5];
    ep.s[2] = (const int*)d_in[6];  ep.d[2] = (const int*)d_in[7];
    ep.s[3] = (const int*)d_in[8];  ep.d[3] = (const int*)d_in[9];
    ep.s[4] = (const int*)d_in[10]; ep.d[4] = (const int*)d_in[11];
    ep.s[5] = (const int*)d_in[12]; ep.d[5] = (const int*)d_in[13];
    ep.s[6] = (const int*)d_in[14]; ep.d[6] = (const int*)d_in[15];

    const int N3 = in_sizes[2];
    const int N4 = in_sizes[6];
    int b = 0;
    for (int r = 0; r < 7; r++) {
        ep.ebase[r] = b;
        b += (r < 2) ? N3 : N4;
    }
    ep.ebase[7] = b;

    // bucket capacities: full relation size each (cannot overflow)
    SlotBases sb;
    {
        int acc = 0;
        for (int r = 0; r < 7; r++) {
            int ne  = (r < 2) ? N3 : N4;
            int nch = (r < 2) ? 2 : 3;
            for (int c = 0; c < 3; c++) {
                sb.b[r * 3 + c] = acc;
                if (c < nch) acc += ne;
            }
        }
    }

    float* out = (float*)d_out;

    init_cur_kernel<<<1, 32>>>();
    partition_kernel<<<(int)((TOT + 255) / 256), 256>>>(ep, sb);

    float* o = out;
    for (int r = 0; r < 7; r++) {
        const float* feat = (r < 5) ? u2 : u3;
        int rows = (r < 2) ? N3 : N4;
        int ne   = (r < 2) ? N3 : N4;
        int nch  = (r < 2) ? 2 : 3;
        int cdiv = (rows + nch - 1) / nch;

        for (int c = 0; c < nch; c++) {
            int lo = c * cdiv;
            int rows_c = min(cdiv, rows - lo);
            // zero this chunk (<=96MB -> stays dirty in L2)
            long long n4 = (long long)rows_c * 8;
            zero_f4_kernel<<<(int)((n4 + 255) / 256), 256>>>(
                (float4*)(o + (long long)lo * FEAT_D), n4);

            // scatter this bucket's edges only
            int maxp = ne / nch + (ne / nch) / 8 + 4096;  // ~+12.5% margin
            int half = (maxp + 1) / 2;
            long long threads = (long long)half * 8;
            int grid = (int)((threads + 255) / 256);
            scatter_bucket_kernel<<<grid, 256>>>(
                (const float4*)feat, o, sb.b[r * 3 + c], r * 3 + c, half);
        }
        o += (long long)rows * FEAT_D;
    }
}

// round 12
// speedup vs baseline: 1.3112x; 1.3112x over previous
#include <cuda_runtime.h>

// ---------------------------------------------------------------------------
// CarryII R12: R6 (best, 858us) + zero/scatter FUSION for DRAM mix overlap.
// R6 serialized pure-write zero kernels (~255us) with read/atomic-heavy
// scatter kernels (70.9% DRAM). Fusion: scatter kernel for relation k also
// zeroes relation k+1's output block via appended tail blocks (disjoint
// memory -> no intra-kernel ordering hazard; kernel boundary preserves
// zero-before-scatter for k+1). Zero write traffic rides in the scatter's
// idle write bandwidth. Only block 0's zero is standalone.
// Scatter path unchanged from R6: 8 lanes/edge, 2 edges/thread, red.v4,
// __ldcs on indices, __ldg on features.
// ---------------------------------------------------------------------------

static constexpr int FEAT_D = 32;

__global__ void zero_f4_kernel(float4* __restrict__ out, long long n4) {
    long long i = blockIdx.x * (long long)blockDim.x + threadIdx.x;
    if (i < n4) out[i] = make_float4(0.f, 0.f, 0.f, 0.f);
}

__device__ __forceinline__ void red_add_v4(float* addr, float4 v) {
    asm volatile("red.global.v4.f32.add [%0], {%1, %2, %3, %4};"
                 :: "l"(addr), "f"(v.x), "f"(v.y), "f"(v.z), "f"(v.w)
                 : "memory");
}

// Scatter for relation k (+ zero of next relation's block in tail threads).
__global__ void scatter_zero_kernel(const float4* __restrict__ feat,
                                    const int* __restrict__ s_idx,
                                    const int* __restrict__ d_idx,
                                    float* __restrict__ out,
                                    int n_edges, int nh,
                                    float4* __restrict__ zptr,  // may be null
                                    long long zn4) {
    long long gid = blockIdx.x * (long long)blockDim.x + threadIdx.x;
    long long scat_threads = (long long)nh * 8;

    if (gid >= scat_threads) {
        long long zi = gid - scat_threads;
        if (zi < zn4) zptr[zi] = make_float4(0.f, 0.f, 0.f, 0.f);
        return;
    }

    int pair = (int)(gid >> 3);
    int sub  = (int)(gid & 7);

    int e0 = pair;
    int e1 = pair + nh;
    bool has1 = (e1 < n_edges);

    int s0 = __ldcs(s_idx + e0);
    int d0 = __ldcs(d_idx + e0);
    int s1 = has1 ? __ldcs(s_idx + e1) : 0;
    int d1 = has1 ? __ldcs(d_idx + e1) : 0;

    float4 v0 = __ldg(feat + (long long)s0 * 8 + sub);
    float4 v1 = has1 ? __ldg(feat + (long long)s1 * 8 + sub)
                     : make_float4(0.f, 0.f, 0.f, 0.f);

    red_add_v4(out + (long long)d0 * FEAT_D + sub * 4, v0);
    if (has1) red_add_v4(out + (long long)d1 * FEAT_D + sub * 4, v1);
}

extern "C" void kernel_launch(void* const* d_in, const int* in_sizes, int n_in,
                              void* d_out, int out_size) {
    const float* u2 = (const float*)d_in[0];
    const float* u3 = (const float*)d_in[1];

    const int* S[7] = {(const int*)d_in[2], (const int*)d_in[4],
                       (const int*)d_in[6], (const int*)d_in[8],
                       (const int*)d_in[10], (const int*)d_in[12],
                       (const int*)d_in[14]};
    const int* D[7] = {(const int*)d_in[3], (const int*)d_in[5],
                       (const int*)d_in[7], (const int*)d_in[9],
                       (const int*)d_in[11], (const int*)d_in[13],
                       (const int*)d_in[15]};

    const int N3 = in_sizes[2];
    const int N4 = in_sizes[6];

    int rows[7], nedge[7];
    const float* feat[7];
    for (int r = 0; r < 7; r++) {
        rows[r]  = (r < 2) ? N3 : N4;
        nedge[r] = rows[r];
        feat[r]  = (r < 5) ? u2 : u3;
    }

    float* out = (float*)d_out;
    float* blk[8];
    {
        float* o = out;
        for (int r = 0; r < 7; r++) {
            blk[r] = o;
            o += (long long)rows[r] * FEAT_D;
        }
        blk[7] = nullptr;
    }

    // standalone zero of block 0
    {
        long long n4 = (long long)rows[0] * 8;
        zero_f4_kernel<<<(int)((n4 + 255) / 256), 256>>>((float4*)blk[0], n4);
    }

    // scatter r, fused with zero of block r+1
    for (int r = 0; r < 7; r++) {
        int nh = (nedge[r] + 1) / 2;
        long long scat_threads = (long long)nh * 8;
        long long zn4 = (r + 1 < 7) ? (long long)rows[r + 1] * 8 : 0;
        float4* zptr = (r + 1 < 7) ? (float4*)blk[r + 1] : nullptr;

        long long total = scat_threads + zn4;
        int grid = (int)((total + 255) / 256);
        scatter_zero_kernel<<<grid, 256>>>((const float4*)feat[r], S[r], D[r],
                                           blk[r], nedge[r], nh, zptr, zn4);
    }
}